// round 5
// baseline (speedup 1.0000x reference)
#include <cuda_runtime.h>
#include <cuda_bf16.h>

// GraphTrainNN: out[b] = prod_g  w2[g] * (w1[g]^2 + w0[g]*x[b,g]^2) / (w1[g]^2 + x[b,g]^2)
// B = 524288 rows, G = 127 genes. x: (B,G) fp32, w: (G,3) fp32 [w0, w1, w2].
//
// R5: persistent blocks + cp.async double-buffered smem staging.
//  - x viewed as flat float4 stream; 64-row tile = 32512 B, 16B-aligned ->
//    perfectly coalesced 16B async copies (no misaligned-sector overhead).
//  - 32.5 KB in flight per block, ~97 KB/SM: load depth decoupled from
//    registers/occupancy.
//  - compute from smem: warp w owns 8 rows; 8 independent product chains,
//    per-lane 4-gene ratio + 1 division/row, 5 butterfly levels interleaved.

#define GG 127
#define RPT 64                         // rows per tile
#define FPT (RPT * GG)                 // floats per tile = 8128
#define F4PT (FPT / 4)                 // float4 per tile = 2032
#define TBYTES (FPT * 4)               // tile bytes = 32512
#define NBLOCKS 444                    // 148 SM * 3

__global__ __launch_bounds__(256)
void hill_smem_kernel(const float* __restrict__ x,
                      const float* __restrict__ w,
                      float* __restrict__ out,
                      int ntiles)
{
    extern __shared__ float sbuf[];    // 2 * FPT floats
    const int tid  = threadIdx.x;
    const int lane = tid & 31;
    const int wib  = tid >> 5;         // warp in block, 0..7

    // ---- per-lane gene parameters ----
    float w0c[4], wnc[4];
    float w2l = 1.0f;
#pragma unroll
    for (int j = 0; j < 4; ++j) {
        const int g = lane + 32 * j;
        if (g < GG) {
            const float a = __ldg(&w[g * 3 + 0]);
            const float k = __ldg(&w[g * 3 + 1]);
            const float s = __ldg(&w[g * 3 + 2]);
            w0c[j] = a;
            wnc[j] = k * k;
            w2l   *= s;
        } else {
            w0c[j] = 0.0f;   // identity gene: num term = den term = 1
            wnc[j] = 1.0f;
        }
    }
#pragma unroll
    for (int o = 16; o; o >>= 1)
        w2l *= __shfl_xor_sync(0xFFFFFFFFu, w2l, o);
    const float W2ALL = w2l;

    const unsigned smem_base =
        (unsigned)__cvta_generic_to_shared(sbuf);

    // ---- stage one tile via cp.async (16B, fully coalesced & aligned) ----
    auto stage = [&](int buf, int tile) {
        const float4* __restrict__ src =
            reinterpret_cast<const float4*>(x) + (size_t)tile * F4PT;
        const unsigned dst = smem_base + buf * TBYTES;
#pragma unroll
        for (int it = 0; it < 8; ++it) {
            const int idx = it * 256 + tid;
            if (idx < F4PT)
                asm volatile("cp.async.cg.shared.global [%0], [%1], 16;\n"
                             :: "r"(dst + idx * 16), "l"(src + idx));
        }
        asm volatile("cp.async.commit_group;\n" ::: "memory");
    };

    // ---- compute one tile from smem ----
    auto compute = [&](int buf, int tile) {
        const float* __restrict__ s = sbuf + buf * FPT + wib * 8 * GG;

        float num[8], den[8];
#pragma unroll
        for (int r = 0; r < 8; ++r) { num[r] = 1.0f; den[r] = 1.0f; }

#pragma unroll
        for (int j = 0; j < 4; ++j) {
            const int g = lane + 32 * j;
#pragma unroll
            for (int r = 0; r < 8; ++r) {
                const float xv = (g < GG) ? s[r * GG + g] : 0.0f;
                const float a  = xv * xv;
                num[r] *= fmaf(w0c[j], a, wnc[j]);   // wn + w0*x^n
                den[r] *= (wnc[j] + a);              // wn + x^n
            }
        }

        float rr[8];
#pragma unroll
        for (int r = 0; r < 8; ++r)
            rr[r] = __fdividef(num[r], den[r]);      // in [~1e-4, 1]

#pragma unroll
        for (int o = 1; o <= 16; o <<= 1)
#pragma unroll
            for (int r = 0; r < 8; ++r)
                rr[r] *= __shfl_xor_sync(0xFFFFFFFFu, rr[r], o);

        if (lane == 0) {
            const int base = tile * RPT + wib * 8;   // multiple of 8
            float4 a, b;
            a.x = W2ALL * rr[0]; a.y = W2ALL * rr[1];
            a.z = W2ALL * rr[2]; a.w = W2ALL * rr[3];
            b.x = W2ALL * rr[4]; b.y = W2ALL * rr[5];
            b.z = W2ALL * rr[6]; b.w = W2ALL * rr[7];
            *reinterpret_cast<float4*>(out + base)     = a;
            *reinterpret_cast<float4*>(out + base + 4) = b;
        }
    };

    // ---- persistent double-buffered tile loop ----
    int t = blockIdx.x;
    if (t >= ntiles) return;
    stage(0, t);

    int buf = 0;
    for (int i = t; i < ntiles; i += gridDim.x, buf ^= 1) {
        const int nxt = i + gridDim.x;
        if (nxt < ntiles) {
            stage(buf ^ 1, nxt);                     // prefetch next tile
            asm volatile("cp.async.wait_group 1;\n" ::: "memory");
        } else {
            asm volatile("cp.async.wait_group 0;\n" ::: "memory");
        }
        __syncthreads();          // tile i ready for all warps
        compute(buf, i);
        __syncthreads();          // all reads done before buf is re-staged
    }
}

extern "C" void kernel_launch(void* const* d_in, const int* in_sizes, int n_in,
                              void* d_out, int out_size)
{
    const float* x = (const float*)d_in[0];   // (B, G) fp32
    const float* w = (const float*)d_in[1];   // (G, 3) fp32
    float* out = (float*)d_out;               // (B, 1) fp32

    const int rows   = in_sizes[0] / GG;      // 524288
    const int ntiles = rows / RPT;            // 8192

    static bool attr_done = false;            // idempotent, deterministic
    cudaFuncSetAttribute(hill_smem_kernel,
                         cudaFuncAttributeMaxDynamicSharedMemorySize,
                         2 * TBYTES);
    (void)attr_done;

    hill_smem_kernel<<<NBLOCKS, 256, 2 * TBYTES>>>(x, w, out, ntiles);
}